// round 9
// baseline (speedup 1.0000x reference)
#include <cuda_runtime.h>
#include <math.h>

// Problem constants
#define P_TOT   16200   // H*W
#define MD      130
#define L       128
#define NH      8
#define S       16
#define K       25
#define NNB     25
#define MH      32
#define FH      256

// Scratch (allocation-free: __device__ globals)
__device__ __align__(16) float g_xL  [P_TOT * L];        // packed x[:, :128]
__device__ __align__(16) float g_wp  [P_TOT * NNB * S];  // precomputed W2
__device__ __align__(16) float g_xmix[P_TOT * L];        // x_mix

// fast exact-enough GELU: Abramowitz-Stegun 7.1.26 erf (|abs err| <= 1.5e-7)
__device__ __forceinline__ float gelu_f(float v) {
    const float xa = fabsf(v) * 0.70710678118654752f;
    const float t  = __fdividef(1.0f, fmaf(0.3275911f, xa, 1.0f));
    float poly = fmaf(t, 1.061405429f, -1.453152027f);
    poly = fmaf(t, poly, 1.421413741f);
    poly = fmaf(t, poly, -0.284496736f);
    poly = fmaf(t, poly, 0.254829592f);
    poly *= t;
    const float e = __expf(-xa * xa);
    float erfv = fmaf(-poly, e, 1.0f);
    erfv = copysignf(erfv, v);
    return 0.5f * v * (1.0f + erfv);
}

#define BARG(gid) asm volatile("bar.sync %0, 128;" :: "r"((gid) + 1) : "memory")

// ============================================================================
// Kernel X: pack x[:, :128] -> g_xL ; sincos -> out
// ============================================================================
__global__ void __launch_bounds__(256) pack_kernel(
    const float* __restrict__ x, float* __restrict__ out)
{
    const int tid = blockIdx.x * 256 + threadIdx.x;
    if (tid < P_TOT * 32) {
        const int p = tid >> 5, c4 = tid & 31;
        const float* src = &x[p * MD + c4 * 4];
        *(float4*)&g_xL[p * L + c4 * 4] = make_float4(src[0], src[1], src[2], src[3]);
    }
    if (tid < P_TOT * 2) {
        const int p = tid >> 1, c = tid & 1;
        out[p * MD + L + c] = x[p * MD + L + c];
    }
}

// ============================================================================
// Kernel W: wp[p][n][s] = sum_k dw[s][k] * basis[k][p][n]
// ============================================================================
__global__ void __launch_bounds__(256) wp_kernel(
    const float* __restrict__ basis,
    const float* __restrict__ dw)
{
    __shared__ __align__(16) float s_dw[S * K];
    const int t = threadIdx.x;
    for (int i = t; i < S * K; i += 256) s_dw[i] = dw[i];
    __syncthreads();

    const int pp = t >> 5, n = t & 31;
    const int p = blockIdx.x * 8 + pp;
    if (n >= NNB) return;

    float b[K];
    #pragma unroll
    for (int k = 0; k < K; k++)
        b[k] = basis[(k * P_TOT + p) * NNB + n];

    float acc[S];
    #pragma unroll
    for (int s = 0; s < S; s++) {
        float a = 0.f;
        #pragma unroll
        for (int k = 0; k < K; k++)
            a = fmaf(s_dw[s * K + k], b[k], a);
        acc[s] = a;
    }
    float4* dst = (float4*)&g_wp[(p * NNB + n) * S];
    dst[0] = make_float4(acc[0],  acc[1],  acc[2],  acc[3]);
    dst[1] = make_float4(acc[4],  acc[5],  acc[6],  acc[7]);
    dst[2] = make_float4(acc[8],  acc[9],  acc[10], acc[11]);
    dst[3] = make_float4(acc[12], acc[13], acc[14], acc[15]);
}

// ============================================================================
// Kernel A: smem-staged gather + y GEMV + heads MLP + residual -> g_xmix
//   (unchanged from R8 committed version)
// ============================================================================
#define PPG 5
__global__ void __launch_bounds__(256, 4) disco_heads_kernel(
    const int*   __restrict__ nbr,
    const float* __restrict__ db,
    const float* __restrict__ hw1,
    const float* __restrict__ hb1,
    const float* __restrict__ hw2,
    const float* __restrict__ hb2)
{
    __shared__ __align__(16) float s_db[S];
    __shared__ __align__(16) float s_w1[NH * S * MH];    // 16KB
    __shared__ __align__(16) float s_b1[NH * MH];
    __shared__ __align__(16) float s_w2[NH * MH];
    __shared__ __align__(16) float s_b2[NH];
    __shared__ __align__(16) float s_wp[2][NNB * S];     // [n][s]
    __shared__ __align__(16) float s_G[2][NNB * L];      // [n][c]
    __shared__ int s_nbrs[2][PPG * NNB];

    const int t  = threadIdx.x;
    const int g  = t >> 7;
    const int lt = t & 127;

    if (t < S) s_db[t] = db[t];
    for (int i = t; i < NH * S * MH; i += 256) s_w1[i] = hw1[i];
    for (int i = t; i < NH * MH; i += 256) { s_b1[i] = hb1[i]; s_w2[i] = hw2[i]; }
    if (t < NH) s_b2[t] = hb2[t];

    const int p0 = blockIdx.x * (2 * PPG) + g * PPG;
    for (int i = lt; i < PPG * NNB; i += 128)
        s_nbrs[g][i] = nbr[p0 * NNB + i];
    __syncthreads();

    const int h = lt >> 4;
    const int n4 = lt >> 5, c4 = lt & 31;
    const float4* xL4 = (const float4*)g_xL;
    const float4* wp4 = (const float4*)g_wp;

    for (int ip = 0; ip < PPG; ip++) {
        const int p = p0 + ip;

        BARG(g);  // guard smem reuse

        // gather: 4 neighbors in flight per pass, float4 rows
        #pragma unroll
        for (int nb = n4; nb < NNB; nb += 4) {
            const int q = s_nbrs[g][ip * NNB + nb];
            *(float4*)&s_G[g][nb * L + c4 * 4] = xL4[q * 32 + c4];
        }
        // wp tile: 400 floats = 100 float4
        if (lt < 100)
            *(float4*)&s_wp[g][lt * 4] = wp4[p * 100 + lt];
        BARG(g);

        // y[lt][s] in registers
        float y[16];
        #pragma unroll
        for (int s = 0; s < 16; s++) y[s] = s_db[s];
        #pragma unroll
        for (int n = 0; n < NNB; n++) {
            const float gv = s_G[g][n * L + lt];
            const float4 w0 = *(const float4*)&s_wp[g][n * S + 0];
            const float4 w1v = *(const float4*)&s_wp[g][n * S + 4];
            const float4 w2v = *(const float4*)&s_wp[g][n * S + 8];
            const float4 w3v = *(const float4*)&s_wp[g][n * S + 12];
            y[0]  = fmaf(gv, w0.x,  y[0]);  y[1]  = fmaf(gv, w0.y,  y[1]);
            y[2]  = fmaf(gv, w0.z,  y[2]);  y[3]  = fmaf(gv, w0.w,  y[3]);
            y[4]  = fmaf(gv, w1v.x, y[4]);  y[5]  = fmaf(gv, w1v.y, y[5]);
            y[6]  = fmaf(gv, w1v.z, y[6]);  y[7]  = fmaf(gv, w1v.w, y[7]);
            y[8]  = fmaf(gv, w2v.x, y[8]);  y[9]  = fmaf(gv, w2v.y, y[9]);
            y[10] = fmaf(gv, w2v.z, y[10]); y[11] = fmaf(gv, w2v.w, y[11]);
            y[12] = fmaf(gv, w3v.x, y[12]); y[13] = fmaf(gv, w3v.y, y[13]);
            y[14] = fmaf(gv, w3v.z, y[14]); y[15] = fmaf(gv, w3v.w, y[15]);
        }

        // heads (two m-halves of 16)
        const float* w1h = &s_w1[h * S * MH];
        float hout = s_b2[h];
        #pragma unroll
        for (int half = 0; half < 2; half++) {
            const int mo = half * 16;
            float h1[16];
            #pragma unroll
            for (int j = 0; j < 16; j++) h1[j] = s_b1[h * MH + mo + j];
            #pragma unroll
            for (int s = 0; s < 16; s++) {
                const float ys = y[s];
                const float4* w4 = (const float4*)&w1h[s * MH + mo];
                #pragma unroll
                for (int j4 = 0; j4 < 4; j4++) {
                    const float4 w = w4[j4];
                    h1[j4*4+0] = fmaf(ys, w.x, h1[j4*4+0]);
                    h1[j4*4+1] = fmaf(ys, w.y, h1[j4*4+1]);
                    h1[j4*4+2] = fmaf(ys, w.z, h1[j4*4+2]);
                    h1[j4*4+3] = fmaf(ys, w.w, h1[j4*4+3]);
                }
            }
            #pragma unroll
            for (int j = 0; j < 16; j++)
                hout = fmaf(gelu_f(h1[j]), s_w2[h * MH + mo + j], hout);
        }

        g_xmix[p * L + lt] = hout + g_xL[p * L + lt];
    }
}

// ============================================================================
// Kernel F: fused FFN. 24 pixels/block, 256 threads.
//   ffn_w1 rows 128..129 are ZERO -> K is exactly 128.
//   s_x rows padded to stride 132 -> conflict-free scalar AND float4 LDS.
//   phase1 d-tiled by 4 with float4 LDS (bank groups {0,24,16,8} per pq).
// ============================================================================
#define FP 24
#define XSP 132   // padded s_x row stride
#define HFS 260   // padded hf row stride
__global__ void __launch_bounds__(256, 4) ffn_kernel(
    const float* __restrict__ fw1,
    const float* __restrict__ fb1,
    const float* __restrict__ fw2,
    const float* __restrict__ fb2,
    float* __restrict__ out)
{
    __shared__ __align__(16) float s_x[FP * XSP];   // 12.7 KB
    __shared__ __align__(16) float s_hf[FP * HFS];  // 25.0 KB

    const int t = threadIdx.x;
    const int p0 = blockIdx.x * FP;

    // x tile: float4 copy of g_xmix rows into padded-stride smem
    {
        const float4* src = (const float4*)&g_xmix[p0 * L];
        #pragma unroll
        for (int i = t; i < FP * 32; i += 256) {
            const int pp = i >> 5, c4 = i & 31;
            *(float4*)&s_x[pp * XSP + c4 * 4] = src[i];
        }
    }
    __syncthreads();

    // phase 1: f4 = t>>2 (64 groups of 4 f), pq = t&3 (6 pixels each)
    //          d tiled by 4, xv loaded as float4 (conflict-free at stride 132)
    {
        const int f4 = t >> 2, pq = t & 3;
        const float4 bb = *(const float4*)&fb1[f4 * 4];
        float a0[6], a1[6], a2[6], a3[6];
        #pragma unroll
        for (int j = 0; j < 6; j++) { a0[j] = bb.x; a1[j] = bb.y; a2[j] = bb.z; a3[j] = bb.w; }

        #pragma unroll 4
        for (int d4 = 0; d4 < L / 4; d4++) {
            const float4 w0 = __ldg((const float4*)&fw1[(d4 * 4 + 0) * FH + f4 * 4]);
            const float4 w1 = __ldg((const float4*)&fw1[(d4 * 4 + 1) * FH + f4 * 4]);
            const float4 w2 = __ldg((const float4*)&fw1[(d4 * 4 + 2) * FH + f4 * 4]);
            const float4 w3 = __ldg((const float4*)&fw1[(d4 * 4 + 3) * FH + f4 * 4]);
            #pragma unroll
            for (int j = 0; j < 6; j++) {
                const float4 xv = *(const float4*)&s_x[(pq * 6 + j) * XSP + d4 * 4];
                a0[j] = fmaf(xv.x, w0.x, a0[j]);
                a1[j] = fmaf(xv.x, w0.y, a1[j]);
                a2[j] = fmaf(xv.x, w0.z, a2[j]);
                a3[j] = fmaf(xv.x, w0.w, a3[j]);
                a0[j] = fmaf(xv.y, w1.x, a0[j]);
                a1[j] = fmaf(xv.y, w1.y, a1[j]);
                a2[j] = fmaf(xv.y, w1.z, a2[j]);
                a3[j] = fmaf(xv.y, w1.w, a3[j]);
                a0[j] = fmaf(xv.z, w2.x, a0[j]);
                a1[j] = fmaf(xv.z, w2.y, a1[j]);
                a2[j] = fmaf(xv.z, w2.z, a2[j]);
                a3[j] = fmaf(xv.z, w2.w, a3[j]);
                a0[j] = fmaf(xv.w, w3.x, a0[j]);
                a1[j] = fmaf(xv.w, w3.y, a1[j]);
                a2[j] = fmaf(xv.w, w3.z, a2[j]);
                a3[j] = fmaf(xv.w, w3.w, a3[j]);
            }
        }
        #pragma unroll
        for (int j = 0; j < 6; j++) {
            float4 hv;
            hv.x = gelu_f(a0[j]); hv.y = gelu_f(a1[j]);
            hv.z = gelu_f(a2[j]); hv.w = gelu_f(a3[j]);
            *(float4*)&s_hf[(pq * 6 + j) * HFS + f4 * 4] = hv;
        }
    }
    __syncthreads();

    // phase 2: l4 = t>>3 (32 groups of 4 L), pg = t&7 (3 pixels each), scalar f
    {
        const int l4 = t >> 3, pg = t & 7;
        const float4 bb = *(const float4*)&fb2[l4 * 4];
        float a0[3], a1[3], a2[3], a3[3];
        #pragma unroll
        for (int j = 0; j < 3; j++) { a0[j] = bb.x; a1[j] = bb.y; a2[j] = bb.z; a3[j] = bb.w; }

        for (int f = 0; f < FH; f++) {
            const float4 w = __ldg((const float4*)&fw2[f * L + l4 * 4]);
            #pragma unroll
            for (int j = 0; j < 3; j++) {
                const float hv = s_hf[(pg * 3 + j) * HFS + f];
                a0[j] = fmaf(hv, w.x, a0[j]);
                a1[j] = fmaf(hv, w.y, a1[j]);
                a2[j] = fmaf(hv, w.z, a2[j]);
                a3[j] = fmaf(hv, w.w, a3[j]);
            }
        }
        #pragma unroll
        for (int j = 0; j < 3; j++) {
            const int p = p0 + pg * 3 + j;
            const float4 r = *(const float4*)&s_x[(pg * 3 + j) * XSP + l4 * 4];
            float* o = &out[p * MD + l4 * 4];
            o[0] = a0[j] + r.x;
            o[1] = a1[j] + r.y;
            o[2] = a2[j] + r.z;
            o[3] = a3[j] + r.w;
        }
    }
}

// ============================================================================
// Launch
// ============================================================================
extern "C" void kernel_launch(void* const* d_in, const int* in_sizes, int n_in,
                              void* d_out, int out_size)
{
    const float* x     = (const float*)d_in[0];
    const int*   nbr   = (const int*)  d_in[1];
    const float* basis = (const float*)d_in[2];
    const float* dw    = (const float*)d_in[3];
    const float* db    = (const float*)d_in[4];
    const float* hw1   = (const float*)d_in[5];
    const float* hb1   = (const float*)d_in[6];
    const float* hw2   = (const float*)d_in[7];
    const float* hb2   = (const float*)d_in[8];
    const float* fw1   = (const float*)d_in[9];
    const float* fb1   = (const float*)d_in[10];
    const float* fw2   = (const float*)d_in[11];
    const float* fb2   = (const float*)d_in[12];
    float* out = (float*)d_out;

    pack_kernel<<<(P_TOT * 32 + 255) / 256, 256>>>(x, out);
    wp_kernel<<<P_TOT / 8, 256>>>(basis, dw);
    disco_heads_kernel<<<P_TOT / (2 * PPG), 256>>>(nbr, db, hw1, hb1, hw2, hb2);
    ffn_kernel<<<P_TOT / FP, 256>>>(fw1, fb1, fw2, fb2, out);
}

// round 10
// speedup vs baseline: 1.6355x; 1.6355x over previous
#include <cuda_runtime.h>
#include <math.h>

// Problem constants
#define P_TOT   16200   // H*W
#define MD      130
#define L       128
#define NH      8
#define S       16
#define K       25
#define NNB     25
#define MH      32
#define FH      256

// Scratch (allocation-free: __device__ globals)
__device__ __align__(16) float g_xL  [P_TOT * L];        // packed x[:, :128]
__device__ __align__(16) float g_wp  [P_TOT * NNB * S];  // precomputed W2
__device__ __align__(16) float g_xmix[P_TOT * L];        // x_mix

// fast exact-enough GELU: Abramowitz-Stegun 7.1.26 erf (|abs err| <= 1.5e-7)
__device__ __forceinline__ float gelu_f(float v) {
    const float xa = fabsf(v) * 0.70710678118654752f;
    const float t  = __fdividef(1.0f, fmaf(0.3275911f, xa, 1.0f));
    float poly = fmaf(t, 1.061405429f, -1.453152027f);
    poly = fmaf(t, poly, 1.421413741f);
    poly = fmaf(t, poly, -0.284496736f);
    poly = fmaf(t, poly, 0.254829592f);
    poly *= t;
    const float e = __expf(-xa * xa);
    float erfv = fmaf(-poly, e, 1.0f);
    erfv = copysignf(erfv, v);
    return 0.5f * v * (1.0f + erfv);
}

#define BARG(gid) asm volatile("bar.sync %0, 128;" :: "r"((gid) + 1) : "memory")

// ============================================================================
// Kernel X: pack x[:, :128] -> g_xL ; sincos -> out
// ============================================================================
__global__ void __launch_bounds__(256) pack_kernel(
    const float* __restrict__ x, float* __restrict__ out)
{
    const int tid = blockIdx.x * 256 + threadIdx.x;
    if (tid < P_TOT * 32) {
        const int p = tid >> 5, c4 = tid & 31;
        const float* src = &x[p * MD + c4 * 4];
        *(float4*)&g_xL[p * L + c4 * 4] = make_float4(src[0], src[1], src[2], src[3]);
    }
    if (tid < P_TOT * 2) {
        const int p = tid >> 1, c = tid & 1;
        out[p * MD + L + c] = x[p * MD + L + c];
    }
}

// ============================================================================
// Kernel W: wp[p][n][s] = sum_k dw[s][k] * basis[k][p][n]
// ============================================================================
__global__ void __launch_bounds__(256) wp_kernel(
    const float* __restrict__ basis,
    const float* __restrict__ dw)
{
    __shared__ __align__(16) float s_dw[S * K];
    const int t = threadIdx.x;
    for (int i = t; i < S * K; i += 256) s_dw[i] = dw[i];
    __syncthreads();

    const int pp = t >> 5, n = t & 31;
    const int p = blockIdx.x * 8 + pp;
    if (n >= NNB) return;

    float b[K];
    #pragma unroll
    for (int k = 0; k < K; k++)
        b[k] = basis[(k * P_TOT + p) * NNB + n];

    float acc[S];
    #pragma unroll
    for (int s = 0; s < S; s++) {
        float a = 0.f;
        #pragma unroll
        for (int k = 0; k < K; k++)
            a = fmaf(s_dw[s * K + k], b[k], a);
        acc[s] = a;
    }
    float4* dst = (float4*)&g_wp[(p * NNB + n) * S];
    dst[0] = make_float4(acc[0],  acc[1],  acc[2],  acc[3]);
    dst[1] = make_float4(acc[4],  acc[5],  acc[6],  acc[7]);
    dst[2] = make_float4(acc[8],  acc[9],  acc[10], acc[11]);
    dst[3] = make_float4(acc[12], acc[13], acc[14], acc[15]);
}

// ============================================================================
// Kernel A: smem-staged gather + y GEMV + heads MLP + residual -> g_xmix
//   256 threads = 2 independent 128-thread groups; lane = channel.
//   PPG=9 (18 pixels/block, 900 blocks) to amortize weight staging.
// ============================================================================
#define PPG 9
__global__ void __launch_bounds__(256, 4) disco_heads_kernel(
    const int*   __restrict__ nbr,
    const float* __restrict__ db,
    const float* __restrict__ hw1,
    const float* __restrict__ hb1,
    const float* __restrict__ hw2,
    const float* __restrict__ hb2)
{
    __shared__ __align__(16) float s_db[S];
    __shared__ __align__(16) float s_w1[NH * S * MH];    // 16KB
    __shared__ __align__(16) float s_b1[NH * MH];
    __shared__ __align__(16) float s_w2[NH * MH];
    __shared__ __align__(16) float s_b2[NH];
    __shared__ __align__(16) float s_wp[2][NNB * S];     // [n][s]
    __shared__ __align__(16) float s_G[2][NNB * L];      // [n][c]
    __shared__ int s_nbrs[2][PPG * NNB];

    const int t  = threadIdx.x;
    const int g  = t >> 7;
    const int lt = t & 127;

    if (t < S) s_db[t] = db[t];
    for (int i = t; i < NH * S * MH; i += 256) s_w1[i] = hw1[i];
    for (int i = t; i < NH * MH; i += 256) { s_b1[i] = hb1[i]; s_w2[i] = hw2[i]; }
    if (t < NH) s_b2[t] = hb2[t];

    const int p0 = blockIdx.x * (2 * PPG) + g * PPG;
    for (int i = lt; i < PPG * NNB; i += 128)
        s_nbrs[g][i] = nbr[p0 * NNB + i];
    __syncthreads();

    const int h = lt >> 4;
    const int n4 = lt >> 5, c4 = lt & 31;
    const float4* xL4 = (const float4*)g_xL;
    const float4* wp4 = (const float4*)g_wp;

    for (int ip = 0; ip < PPG; ip++) {
        const int p = p0 + ip;

        BARG(g);  // guard smem reuse

        // gather: 4 neighbors in flight per pass, float4 rows
        #pragma unroll
        for (int nb = n4; nb < NNB; nb += 4) {
            const int q = s_nbrs[g][ip * NNB + nb];
            *(float4*)&s_G[g][nb * L + c4 * 4] = xL4[q * 32 + c4];
        }
        // wp tile: 400 floats = 100 float4
        if (lt < 100)
            *(float4*)&s_wp[g][lt * 4] = wp4[p * 100 + lt];
        BARG(g);

        // y[lt][s] in registers
        float y[16];
        #pragma unroll
        for (int s = 0; s < 16; s++) y[s] = s_db[s];
        #pragma unroll
        for (int n = 0; n < NNB; n++) {
            const float gv = s_G[g][n * L + lt];
            const float4 w0 = *(const float4*)&s_wp[g][n * S + 0];
            const float4 w1v = *(const float4*)&s_wp[g][n * S + 4];
            const float4 w2v = *(const float4*)&s_wp[g][n * S + 8];
            const float4 w3v = *(const float4*)&s_wp[g][n * S + 12];
            y[0]  = fmaf(gv, w0.x,  y[0]);  y[1]  = fmaf(gv, w0.y,  y[1]);
            y[2]  = fmaf(gv, w0.z,  y[2]);  y[3]  = fmaf(gv, w0.w,  y[3]);
            y[4]  = fmaf(gv, w1v.x, y[4]);  y[5]  = fmaf(gv, w1v.y, y[5]);
            y[6]  = fmaf(gv, w1v.z, y[6]);  y[7]  = fmaf(gv, w1v.w, y[7]);
            y[8]  = fmaf(gv, w2v.x, y[8]);  y[9]  = fmaf(gv, w2v.y, y[9]);
            y[10] = fmaf(gv, w2v.z, y[10]); y[11] = fmaf(gv, w2v.w, y[11]);
            y[12] = fmaf(gv, w3v.x, y[12]); y[13] = fmaf(gv, w3v.y, y[13]);
            y[14] = fmaf(gv, w3v.z, y[14]); y[15] = fmaf(gv, w3v.w, y[15]);
        }

        // heads (two m-halves of 16)
        const float* w1h = &s_w1[h * S * MH];
        float hout = s_b2[h];
        #pragma unroll
        for (int half = 0; half < 2; half++) {
            const int mo = half * 16;
            float h1[16];
            #pragma unroll
            for (int j = 0; j < 16; j++) h1[j] = s_b1[h * MH + mo + j];
            #pragma unroll
            for (int s = 0; s < 16; s++) {
                const float ys = y[s];
                const float4* w4 = (const float4*)&w1h[s * MH + mo];
                #pragma unroll
                for (int j4 = 0; j4 < 4; j4++) {
                    const float4 w = w4[j4];
                    h1[j4*4+0] = fmaf(ys, w.x, h1[j4*4+0]);
                    h1[j4*4+1] = fmaf(ys, w.y, h1[j4*4+1]);
                    h1[j4*4+2] = fmaf(ys, w.z, h1[j4*4+2]);
                    h1[j4*4+3] = fmaf(ys, w.w, h1[j4*4+3]);
                }
            }
            #pragma unroll
            for (int j = 0; j < 16; j++)
                hout = fmaf(gelu_f(h1[j]), s_w2[h * MH + mo + j], hout);
        }

        g_xmix[p * L + lt] = hout + g_xL[p * L + lt];
    }
}

// ============================================================================
// Kernel F: fused FFN (R8 committed version, measured 77.4us). 24 px/block.
//   ffn_w1 rows 128..129 are ZERO -> K is exactly 128.
//   s_x rows padded to stride 132 (conflict-free scalar LDS).
// ============================================================================
#define FP 24
#define XSP 132   // padded s_x row stride
#define HFS 260   // padded hf row stride
__global__ void __launch_bounds__(256) ffn_kernel(
    const float* __restrict__ fw1,
    const float* __restrict__ fb1,
    const float* __restrict__ fw2,
    const float* __restrict__ fb2,
    float* __restrict__ out)
{
    __shared__ __align__(16) float s_x[FP * XSP];   // 12.7 KB
    __shared__ __align__(16) float s_hf[FP * HFS];  // 25.0 KB

    const int t = threadIdx.x;
    const int p0 = blockIdx.x * FP;

    // x tile: float4 copy of g_xmix rows into padded-stride smem
    {
        const float4* src = (const float4*)&g_xmix[p0 * L];
        #pragma unroll
        for (int i = t; i < FP * 32; i += 256) {
            const int pp = i >> 5, c4 = i & 31;
            *(float4*)&s_x[pp * XSP + c4 * 4] = src[i];
        }
    }
    __syncthreads();

    // phase 1: f4 = t>>2 (64 groups of 4 f), pq = t&3 (6 pixels each)
    {
        const int f4 = t >> 2, pq = t & 3;
        const float4 bb = *(const float4*)&fb1[f4 * 4];
        float a0[6], a1[6], a2[6], a3[6];
        #pragma unroll
        for (int j = 0; j < 6; j++) { a0[j] = bb.x; a1[j] = bb.y; a2[j] = bb.z; a3[j] = bb.w; }

        for (int d = 0; d < L; d++) {
            const float4 w = __ldg((const float4*)&fw1[d * FH + f4 * 4]);
            #pragma unroll
            for (int j = 0; j < 6; j++) {
                const float xv = s_x[(pq * 6 + j) * XSP + d];
                a0[j] = fmaf(xv, w.x, a0[j]);
                a1[j] = fmaf(xv, w.y, a1[j]);
                a2[j] = fmaf(xv, w.z, a2[j]);
                a3[j] = fmaf(xv, w.w, a3[j]);
            }
        }
        #pragma unroll
        for (int j = 0; j < 6; j++) {
            float4 hv;
            hv.x = gelu_f(a0[j]); hv.y = gelu_f(a1[j]);
            hv.z = gelu_f(a2[j]); hv.w = gelu_f(a3[j]);
            *(float4*)&s_hf[(pq * 6 + j) * HFS + f4 * 4] = hv;
        }
    }
    __syncthreads();

    // phase 2: l4 = t>>3 (32 groups of 4 L), pg = t&7 (3 pixels each)
    {
        const int l4 = t >> 3, pg = t & 7;
        const float4 bb = *(const float4*)&fb2[l4 * 4];
        float a0[3], a1[3], a2[3], a3[3];
        #pragma unroll
        for (int j = 0; j < 3; j++) { a0[j] = bb.x; a1[j] = bb.y; a2[j] = bb.z; a3[j] = bb.w; }

        for (int f = 0; f < FH; f++) {
            const float4 w = __ldg((const float4*)&fw2[f * L + l4 * 4]);
            #pragma unroll
            for (int j = 0; j < 3; j++) {
                const float hv = s_hf[(pg * 3 + j) * HFS + f];
                a0[j] = fmaf(hv, w.x, a0[j]);
                a1[j] = fmaf(hv, w.y, a1[j]);
                a2[j] = fmaf(hv, w.z, a2[j]);
                a3[j] = fmaf(hv, w.w, a3[j]);
            }
        }
        #pragma unroll
        for (int j = 0; j < 3; j++) {
            const int p = p0 + pg * 3 + j;
            const float4 r = *(const float4*)&s_x[(pg * 3 + j) * XSP + l4 * 4];
            float* o = &out[p * MD + l4 * 4];
            o[0] = a0[j] + r.x;
            o[1] = a1[j] + r.y;
            o[2] = a2[j] + r.z;
            o[3] = a3[j] + r.w;
        }
    }
}

// ============================================================================
// Launch
// ============================================================================
extern "C" void kernel_launch(void* const* d_in, const int* in_sizes, int n_in,
                              void* d_out, int out_size)
{
    const float* x     = (const float*)d_in[0];
    const int*   nbr   = (const int*)  d_in[1];
    const float* basis = (const float*)d_in[2];
    const float* dw    = (const float*)d_in[3];
    const float* db    = (const float*)d_in[4];
    const float* hw1   = (const float*)d_in[5];
    const float* hb1   = (const float*)d_in[6];
    const float* hw2   = (const float*)d_in[7];
    const float* hb2   = (const float*)d_in[8];
    const float* fw1   = (const float*)d_in[9];
    const float* fb1   = (const float*)d_in[10];
    const float* fw2   = (const float*)d_in[11];
    const float* fb2   = (const float*)d_in[12];
    float* out = (float*)d_out;

    pack_kernel<<<(P_TOT * 32 + 255) / 256, 256>>>(x, out);
    wp_kernel<<<P_TOT / 8, 256>>>(basis, dw);
    disco_heads_kernel<<<P_TOT / (2 * PPG), 256>>>(nbr, db, hw1, hb1, hw2, hb2);
    ffn_kernel<<<P_TOT / FP, 256>>>(fw1, fb1, fw2, fb2, out);
}

// round 11
// speedup vs baseline: 1.6601x; 1.0150x over previous
#include <cuda_runtime.h>
#include <math.h>

// Problem constants
#define P_TOT   16200   // H*W
#define MD      130
#define L       128
#define NH      8
#define S       16
#define K       25
#define NNB     25
#define MH      32
#define FH      256

// Scratch (allocation-free: __device__ globals)
__device__ __align__(16) float g_xL  [P_TOT * L];        // packed x[:, :128]
__device__ __align__(16) float g_wp  [P_TOT * NNB * S];  // precomputed W2
__device__ __align__(16) float g_xmix[P_TOT * L];        // x_mix

// fast exact-enough GELU: Abramowitz-Stegun 7.1.26 erf (|abs err| <= 1.5e-7)
__device__ __forceinline__ float gelu_f(float v) {
    const float xa = fabsf(v) * 0.70710678118654752f;
    const float t  = __fdividef(1.0f, fmaf(0.3275911f, xa, 1.0f));
    float poly = fmaf(t, 1.061405429f, -1.453152027f);
    poly = fmaf(t, poly, 1.421413741f);
    poly = fmaf(t, poly, -0.284496736f);
    poly = fmaf(t, poly, 0.254829592f);
    poly *= t;
    const float e = __expf(-xa * xa);
    float erfv = fmaf(-poly, e, 1.0f);
    erfv = copysignf(erfv, v);
    return 0.5f * v * (1.0f + erfv);
}

#define BARG(gid) asm volatile("bar.sync %0, 128;" :: "r"((gid) + 1) : "memory")

// ============================================================================
// Kernel X: pack x[:, :128] -> g_xL ; sincos -> out
// ============================================================================
__global__ void __launch_bounds__(256) pack_kernel(
    const float* __restrict__ x, float* __restrict__ out)
{
    const int tid = blockIdx.x * 256 + threadIdx.x;
    if (tid < P_TOT * 32) {
        const int p = tid >> 5, c4 = tid & 31;
        const float* src = &x[p * MD + c4 * 4];
        *(float4*)&g_xL[p * L + c4 * 4] = make_float4(src[0], src[1], src[2], src[3]);
    }
    if (tid < P_TOT * 2) {
        const int p = tid >> 1, c = tid & 1;
        out[p * MD + L + c] = x[p * MD + L + c];
    }
}

// ============================================================================
// Kernel W: wp[p][n][s] = sum_k dw[s][k] * basis[k][p][n]
// ============================================================================
__global__ void __launch_bounds__(256) wp_kernel(
    const float* __restrict__ basis,
    const float* __restrict__ dw)
{
    __shared__ __align__(16) float s_dw[S * K];
    const int t = threadIdx.x;
    for (int i = t; i < S * K; i += 256) s_dw[i] = dw[i];
    __syncthreads();

    const int pp = t >> 5, n = t & 31;
    const int p = blockIdx.x * 8 + pp;
    if (n >= NNB) return;

    float b[K];
    #pragma unroll
    for (int k = 0; k < K; k++)
        b[k] = basis[(k * P_TOT + p) * NNB + n];

    float acc[S];
    #pragma unroll
    for (int s = 0; s < S; s++) {
        float a = 0.f;
        #pragma unroll
        for (int k = 0; k < K; k++)
            a = fmaf(s_dw[s * K + k], b[k], a);
        acc[s] = a;
    }
    float4* dst = (float4*)&g_wp[(p * NNB + n) * S];
    dst[0] = make_float4(acc[0],  acc[1],  acc[2],  acc[3]);
    dst[1] = make_float4(acc[4],  acc[5],  acc[6],  acc[7]);
    dst[2] = make_float4(acc[8],  acc[9],  acc[10], acc[11]);
    dst[3] = make_float4(acc[12], acc[13], acc[14], acc[15]);
}

// ============================================================================
// Kernel A: register gather + double-buffered wp + heads MLP -> g_xmix
//   256 threads = 2 independent 128-thread groups; lane = channel.
//   One barrier per pixel: wp[ip+1] prefetched into alternate buffer while
//   computing pixel ip; gather goes straight to registers (MLP=25).
// ============================================================================
#define PPG 9
__global__ void __launch_bounds__(256, 3) disco_heads_kernel(
    const int*   __restrict__ nbr,
    const float* __restrict__ db,
    const float* __restrict__ hw1,
    const float* __restrict__ hb1,
    const float* __restrict__ hw2,
    const float* __restrict__ hb2)
{
    __shared__ __align__(16) float s_db[S];
    __shared__ __align__(16) float s_w1[NH * S * MH];    // 16KB
    __shared__ __align__(16) float s_b1[NH * MH];
    __shared__ __align__(16) float s_w2[NH * MH];
    __shared__ __align__(16) float s_b2[NH];
    __shared__ __align__(16) float s_wp[2][2][NNB * S];  // [group][buf][n*16+s]
    __shared__ int s_nbrs[2][PPG * NNB];

    const int t  = threadIdx.x;
    const int g  = t >> 7;
    const int lt = t & 127;

    if (t < S) s_db[t] = db[t];
    for (int i = t; i < NH * S * MH; i += 256) s_w1[i] = hw1[i];
    for (int i = t; i < NH * MH; i += 256) { s_b1[i] = hb1[i]; s_w2[i] = hw2[i]; }
    if (t < NH) s_b2[t] = hb2[t];

    const int p0 = blockIdx.x * (2 * PPG) + g * PPG;
    for (int i = lt; i < PPG * NNB; i += 128)
        s_nbrs[g][i] = nbr[p0 * NNB + i];

    const int h = lt >> 4;
    const float4* wp4 = (const float4*)g_wp;

    // stage wp for pixel 0
    if (lt < 100)
        *(float4*)&s_wp[g][0][lt * 4] = wp4[p0 * 100 + lt];
    __syncthreads();

    for (int ip = 0; ip < PPG; ip++) {
        const int p = p0 + ip;
        const int buf = ip & 1;

        // prefetch next pixel's wp into the other buffer (no hazard: other buf)
        if (ip + 1 < PPG && lt < 100)
            *(float4*)&s_wp[g][buf ^ 1][lt * 4] = wp4[(p + 1) * 100 + lt];

        // register gather: 25 independent coalesced LDG.32
        float gv[NNB];
        #pragma unroll
        for (int n = 0; n < NNB; n++)
            gv[n] = __ldg(&g_xL[s_nbrs[g][ip * NNB + n] * L + lt]);

        // y[lt][s] in registers
        const float* wpb = s_wp[g][buf];
        float y[16];
        #pragma unroll
        for (int s = 0; s < 16; s++) y[s] = s_db[s];
        #pragma unroll
        for (int n = 0; n < NNB; n++) {
            const float gvn = gv[n];
            const float4 w0 = *(const float4*)&wpb[n * S + 0];
            const float4 w1v = *(const float4*)&wpb[n * S + 4];
            const float4 w2v = *(const float4*)&wpb[n * S + 8];
            const float4 w3v = *(const float4*)&wpb[n * S + 12];
            y[0]  = fmaf(gvn, w0.x,  y[0]);  y[1]  = fmaf(gvn, w0.y,  y[1]);
            y[2]  = fmaf(gvn, w0.z,  y[2]);  y[3]  = fmaf(gvn, w0.w,  y[3]);
            y[4]  = fmaf(gvn, w1v.x, y[4]);  y[5]  = fmaf(gvn, w1v.y, y[5]);
            y[6]  = fmaf(gvn, w1v.z, y[6]);  y[7]  = fmaf(gvn, w1v.w, y[7]);
            y[8]  = fmaf(gvn, w2v.x, y[8]);  y[9]  = fmaf(gvn, w2v.y, y[9]);
            y[10] = fmaf(gvn, w2v.z, y[10]); y[11] = fmaf(gvn, w2v.w, y[11]);
            y[12] = fmaf(gvn, w3v.x, y[12]); y[13] = fmaf(gvn, w3v.y, y[13]);
            y[14] = fmaf(gvn, w3v.z, y[14]); y[15] = fmaf(gvn, w3v.w, y[15]);
        }

        // heads (two m-halves of 16)
        const float* w1h = &s_w1[h * S * MH];
        float hout = s_b2[h];
        #pragma unroll
        for (int half = 0; half < 2; half++) {
            const int mo = half * 16;
            float h1[16];
            #pragma unroll
            for (int j = 0; j < 16; j++) h1[j] = s_b1[h * MH + mo + j];
            #pragma unroll
            for (int s = 0; s < 16; s++) {
                const float ys = y[s];
                const float4* w4 = (const float4*)&w1h[s * MH + mo];
                #pragma unroll
                for (int j4 = 0; j4 < 4; j4++) {
                    const float4 w = w4[j4];
                    h1[j4*4+0] = fmaf(ys, w.x, h1[j4*4+0]);
                    h1[j4*4+1] = fmaf(ys, w.y, h1[j4*4+1]);
                    h1[j4*4+2] = fmaf(ys, w.z, h1[j4*4+2]);
                    h1[j4*4+3] = fmaf(ys, w.w, h1[j4*4+3]);
                }
            }
            #pragma unroll
            for (int j = 0; j < 16; j++)
                hout = fmaf(gelu_f(h1[j]), s_w2[h * MH + mo + j], hout);
        }

        g_xmix[p * L + lt] = hout + g_xL[p * L + lt];

        BARG(g);  // wp[buf^1] visible; everyone done with wp[buf]
    }
}

// ============================================================================
// Kernel F: fused FFN (R8/R10 committed version, measured 77.4-77.7us).
// ============================================================================
#define FP 24
#define XSP 132   // padded s_x row stride
#define HFS 260   // padded hf row stride
__global__ void __launch_bounds__(256) ffn_kernel(
    const float* __restrict__ fw1,
    const float* __restrict__ fb1,
    const float* __restrict__ fw2,
    const float* __restrict__ fb2,
    float* __restrict__ out)
{
    __shared__ __align__(16) float s_x[FP * XSP];   // 12.7 KB
    __shared__ __align__(16) float s_hf[FP * HFS];  // 25.0 KB

    const int t = threadIdx.x;
    const int p0 = blockIdx.x * FP;

    // x tile: float4 copy of g_xmix rows into padded-stride smem
    {
        const float4* src = (const float4*)&g_xmix[p0 * L];
        #pragma unroll
        for (int i = t; i < FP * 32; i += 256) {
            const int pp = i >> 5, c4 = i & 31;
            *(float4*)&s_x[pp * XSP + c4 * 4] = src[i];
        }
    }
    __syncthreads();

    // phase 1: f4 = t>>2 (64 groups of 4 f), pq = t&3 (6 pixels each)
    {
        const int f4 = t >> 2, pq = t & 3;
        const float4 bb = *(const float4*)&fb1[f4 * 4];
        float a0[6], a1[6], a2[6], a3[6];
        #pragma unroll
        for (int j = 0; j < 6; j++) { a0[j] = bb.x; a1[j] = bb.y; a2[j] = bb.z; a3[j] = bb.w; }

        for (int d = 0; d < L; d++) {
            const float4 w = __ldg((const float4*)&fw1[d * FH + f4 * 4]);
            #pragma unroll
            for (int j = 0; j < 6; j++) {
                const float xv = s_x[(pq * 6 + j) * XSP + d];
                a0[j] = fmaf(xv, w.x, a0[j]);
                a1[j] = fmaf(xv, w.y, a1[j]);
                a2[j] = fmaf(xv, w.z, a2[j]);
                a3[j] = fmaf(xv, w.w, a3[j]);
            }
        }
        #pragma unroll
        for (int j = 0; j < 6; j++) {
            float4 hv;
            hv.x = gelu_f(a0[j]); hv.y = gelu_f(a1[j]);
            hv.z = gelu_f(a2[j]); hv.w = gelu_f(a3[j]);
            *(float4*)&s_hf[(pq * 6 + j) * HFS + f4 * 4] = hv;
        }
    }
    __syncthreads();

    // phase 2: l4 = t>>3 (32 groups of 4 L), pg = t&7 (3 pixels each)
    {
        const int l4 = t >> 3, pg = t & 7;
        const float4 bb = *(const float4*)&fb2[l4 * 4];
        float a0[3], a1[3], a2[3], a3[3];
        #pragma unroll
        for (int j = 0; j < 3; j++) { a0[j] = bb.x; a1[j] = bb.y; a2[j] = bb.z; a3[j] = bb.w; }

        for (int f = 0; f < FH; f++) {
            const float4 w = __ldg((const float4*)&fw2[f * L + l4 * 4]);
            #pragma unroll
            for (int j = 0; j < 3; j++) {
                const float hv = s_hf[(pg * 3 + j) * HFS + f];
                a0[j] = fmaf(hv, w.x, a0[j]);
                a1[j] = fmaf(hv, w.y, a1[j]);
                a2[j] = fmaf(hv, w.z, a2[j]);
                a3[j] = fmaf(hv, w.w, a3[j]);
            }
        }
        #pragma unroll
        for (int j = 0; j < 3; j++) {
            const int p = p0 + pg * 3 + j;
            const float4 r = *(const float4*)&s_x[(pg * 3 + j) * XSP + l4 * 4];
            float* o = &out[p * MD + l4 * 4];
            o[0] = a0[j] + r.x;
            o[1] = a1[j] + r.y;
            o[2] = a2[j] + r.z;
            o[3] = a3[j] + r.w;
        }
    }
}

// ============================================================================
// Launch
// ============================================================================
extern "C" void kernel_launch(void* const* d_in, const int* in_sizes, int n_in,
                              void* d_out, int out_size)
{
    const float* x     = (const float*)d_in[0];
    const int*   nbr   = (const int*)  d_in[1];
    const float* basis = (const float*)d_in[2];
    const float* dw    = (const float*)d_in[3];
    const float* db    = (const float*)d_in[4];
    const float* hw1   = (const float*)d_in[5];
    const float* hb1   = (const float*)d_in[6];
    const float* hw2   = (const float*)d_in[7];
    const float* hb2   = (const float*)d_in[8];
    const float* fw1   = (const float*)d_in[9];
    const float* fb1   = (const float*)d_in[10];
    const float* fw2   = (const float*)d_in[11];
    const float* fb2   = (const float*)d_in[12];
    float* out = (float*)d_out;

    pack_kernel<<<(P_TOT * 32 + 255) / 256, 256>>>(x, out);
    wp_kernel<<<P_TOT / 8, 256>>>(basis, dw);
    disco_heads_kernel<<<P_TOT / (2 * PPG), 256>>>(nbr, db, hw1, hb1, hw2, hb2);
    ffn_kernel<<<P_TOT / FP, 256>>>(fw1, fb1, fw2, fb2, out);
}